// round 14
// baseline (speedup 1.0000x reference)
#include <cuda_runtime.h>
#include <cuda_fp16.h>
#include <cstdint>

// DynamicPointConvBackBone via mma.sync (base-ISA HMMA; tcgen05 unavailable on
// the harness's compute_103 PTX target).
// Resample-first: only B*K rows computed. GEMM [8192 x 1728] @ [1728 x 128]
// in single-pass fp16 (W pre-scaled by 2^14; accumulators unscaled before LN),
// fp32 accumulate. LayerNorm(eps=1e-3)+ReLU epilogue + coords output.
// R13: B operand never touches shared memory — prep kernel writes per-thread
// MMA B-fragment words (PTX m16n8k16 layout) to a gmem table; compute warps
// LDG.128 their fragments directly (L2-resident, shared by all CTAs).
// A stays in a 2-buffer smem ring (one barrier/chunk). Warp tile m32xn32
// (TILE_M=64, 8 warps = 2mw x 4nw) halves A LDSM duplication.

#define TILE_M 64
#define NTH    256
#define IDXP   28
#define MAXCH  28
#define CHUNK  64        // = Cin
#define ATB    16384     // A tile bytes (64 rows x 64 fp16 x 2B) = 8192... (2 bufs below)
#undef  ATB
#define ATB    8192      // A tile bytes (64 rows x 128B)
#define WSCALE 16384.0f
#define WINV   (1.0f / 16384.0f)

// dynamic smem layout
#define SM_A   0                              // 2 x 8192
#define SM_IDX (SM_A + 2 * ATB)               // 16384
#define SM_SRC (SM_IDX + TILE_M * IDXP * 4)   // 23552
#define SM_VAL (SM_SRC + TILE_M * 4)          // 23808
#define SM_RED (SM_VAL + 64)                  // 23872 (64 rows x 8 floats)
#define SM_GB  (SM_RED + TILE_M * 8 * 4)      // 25920 (gamma 128 + beta 128)
#define SM_TOTAL (SM_GB + 256 * 4)            // 26944

// B fragment table: [chunk][nw(4)][ks(4)] -> 64 uint4 (32 lanes x 32B)
__device__ __align__(16) uint4 g_wf[MAXCH * 4 * 4 * 64];

static __device__ __forceinline__ uint32_t smem_u32(const void* p) {
    uint32_t a;
    asm("{ .reg .u64 t; cvta.to.shared.u64 t, %1; cvt.u32.u64 %0, t; }" : "=r"(a) : "l"(p));
    return a;
}
static __device__ __forceinline__ uint32_t pack_h2(float lo, float hi) {
    uint32_t r;
    asm("cvt.rn.f16x2.f32 %0, %1, %2;" : "=r"(r) : "f"(hi), "f"(lo));
    return r;
}
static __device__ __forceinline__ void ldsm4(uint32_t* r, uint32_t addr) {
    asm volatile("ldmatrix.sync.aligned.m8n8.x4.shared.b16 {%0,%1,%2,%3}, [%4];"
                 : "=r"(r[0]), "=r"(r[1]), "=r"(r[2]), "=r"(r[3]) : "r"(addr));
}
static __device__ __forceinline__ void mma16816(float* d, const uint32_t* a,
                                                uint32_t b0, uint32_t b1) {
    asm volatile(
        "mma.sync.aligned.m16n8k16.row.col.f32.f16.f16.f32 "
        "{%0,%1,%2,%3}, {%4,%5,%6,%7}, {%8,%9}, {%0,%1,%2,%3};"
        : "+f"(d[0]), "+f"(d[1]), "+f"(d[2]), "+f"(d[3])
        : "r"(a[0]), "r"(a[1]), "r"(a[2]), "r"(a[3]), "r"(b0), "r"(b1));
}

// ---------------- prep: W -> per-thread B-fragment words (fp16, x2^14) ------
// uint32 index t: q = t&7 (j = q>>1, r = q&1); lane = (t>>3)&31; ks = (t>>8)&3;
// nw = (t>>10)&3; c = t>>12.
// fragment word = { B[k][n], B[k+1][n] } with k = c*64 + ks*16 + (lane&3)*2 + r*8,
//                                          n = nw*32 + j*8 + (lane>>2).
__global__ void prep_w(const float* __restrict__ W, int total) {
    int t = blockIdx.x * blockDim.x + threadIdx.x;
    if (t >= total) return;
    int q    = t & 7;
    int lane = (t >> 3) & 31;
    int ks   = (t >> 8) & 3;
    int nw   = (t >> 10) & 3;
    int c    = t >> 12;
    int j = q >> 1, r = q & 1;
    int k = c * 64 + ks * 16 + (lane & 3) * 2 + r * 8;
    int n = nw * 32 + j * 8 + (lane >> 2);
    __half2 v = __floats2half2_rn(W[k * 128 + n] * WSCALE,
                                  W[(k + 1) * 128 + n] * WSCALE);
    ((__half2*)g_wf)[t] = v;
}

// ---------------- main fused kernel ----------------
__global__ __launch_bounds__(NTH, 1)
void fused_mma_kernel(
    const float* __restrict__ feat,   // [N, 64]
    const float* __restrict__ coors,  // [M, 3]
    const int*   __restrict__ vidx,   // [M, K3]
    const int*   __restrict__ nums,   // [B]
    const float* __restrict__ gamma,  // [128]
    const float* __restrict__ beta,   // [128]
    float* __restrict__ out_feat,     // [rows_total, 128]
    float* __restrict__ out_coor,     // [rows_total, 4]
    int N, int M, int K3, int B, int K, int rows_total)
{
    extern __shared__ __align__(128) char sm[];
    const uint32_t smb = smem_u32(sm);
    const int tid  = threadIdx.x;
    const int wid  = tid >> 5;
    const int lane = tid & 31;
    const int row0 = blockIdx.x * TILE_M;

    int* s_idx = (int*)(sm + SM_IDX);
    int* s_src = (int*)(sm + SM_SRC);
    unsigned char* s_val = (unsigned char*)(sm + SM_VAL);
    float* s_red = (float*)(sm + SM_RED);
    float* s_gb  = (float*)(sm + SM_GB);

    // per-row source & validity
    if (tid < TILE_M) {
        int r = row0 + tid;
        int src = 0; bool valid = false;
        if (r < rows_total) {
            int b = r / K;
            int j = r - b * K;
            int off = 0;
            for (int i = 0; i < b; ++i) off += nums[i];
            valid = j < min(nums[b], K);
            src   = max(0, min(off + j, M - 1));
        }
        s_src[tid] = src;
        s_val[tid] = valid ? 1 : 0;
    }
    if (tid >= 128) {
        s_gb[tid - 128] = gamma[tid - 128];
        s_gb[tid]       = beta[tid - 128];
    }
    __syncthreads();

    // neighbor indices for this row tile
    for (int i = tid; i < TILE_M * K3; i += NTH) {
        int rr = i / K3, cc = i - rr * K3;
        int v = vidx[(long long)s_src[rr] * K3 + cc];
        s_idx[rr * IDXP + cc] = (v < 0) ? -1 : min(v, N - 1);
    }
    __syncthreads();

    // -------- A loader (gather fp32 -> fp16 swizzled smem) --------
    const int arow = tid >> 2;          // gather row 0..63
    const int aseg = tid & 3;           // 64B segment of 256B fp32 feature row
    float4 pa[4];

    auto a_issue = [&](int c) {
        if (c >= K3) return;
        int gi = s_idx[arow * IDXP + c];
        if (gi >= 0) {
            const float4* src = (const float4*)(feat + (size_t)gi * CHUNK) + aseg * 4;
            pa[0] = __ldg(src + 0); pa[1] = __ldg(src + 1);
            pa[2] = __ldg(src + 2); pa[3] = __ldg(src + 3);
        } else {
            pa[0] = pa[1] = pa[2] = pa[3] = make_float4(0.f, 0.f, 0.f, 0.f);
        }
    };
    auto a_store = [&](int buf) {
        const int sw = arow & 7;
        #pragma unroll
        for (int u = 0; u < 2; ++u) {
            float4 v0 = pa[2 * u], v1 = pa[2 * u + 1];
            uint4 h;
            h.x = pack_h2(v0.x, v0.y);
            h.y = pack_h2(v0.z, v0.w);
            h.z = pack_h2(v1.x, v1.y);
            h.w = pack_h2(v1.z, v1.w);
            const int unit = aseg * 2 + u;
            const int o = arow * 128 + (((unit ^ sw)) << 4);
            *(uint4*)(sm + SM_A + buf * ATB + o) = h;
        }
    };

    // -------- B fragment loader (direct LDG from table) --------
    const int mw = wid & 1, nw = wid >> 1;   // 2 m-warps x 4 n-warps
    const int m0w = mw * 32;

    uint4 bq[2][2];
    auto b_load = [&](int c, int ks, uint4* d) {
        const uint4* p = g_wf + (((size_t)(c * 4 + nw) * 4 + ks) * 64 + lane * 2);
        d[0] = __ldg(p + 0);
        d[1] = __ldg(p + 1);
    };

    // -------- compute --------
    float acc[2][4][4];
    #pragma unroll
    for (int m = 0; m < 2; ++m)
        #pragma unroll
        for (int t = 0; t < 4; ++t)
            #pragma unroll
            for (int qq = 0; qq < 4; ++qq) acc[m][t][qq] = 0.f;

    const int a_hi = lane >> 4;
    const int ar0  = m0w + (lane & 15);
    const int ar1  = ar0 + 16;

    auto compute_ks = [&](int buf, int ks, const uint4* bqc) {
        const uint32_t aB = smb + SM_A + buf * ATB;
        uint32_t ah0[4], ah1[4];
        ldsm4(ah0, aB + (uint32_t)(ar0 * 128 + (((ks * 2 + a_hi) ^ (ar0 & 7)) << 4)));
        ldsm4(ah1, aB + (uint32_t)(ar1 * 128 + (((ks * 2 + a_hi) ^ (ar1 & 7)) << 4)));
        const uint32_t* bb = (const uint32_t*)bqc;
        #pragma unroll
        for (int j = 0; j < 4; ++j) {
            mma16816(acc[0][j], ah0, bb[2 * j], bb[2 * j + 1]);
            mma16816(acc[1][j], ah1, bb[2 * j], bb[2 * j + 1]);
        }
    };

    // -------- main loop: A double-buffered (1 barrier/chunk), B reg-buffered --------
    b_load(0, 0, bq[0]);
    a_issue(0);
    a_store(0);
    __syncthreads();

    for (int c = 0; c < K3; ++c) {
        const int buf = c & 1;
        a_issue(c + 1);
        #pragma unroll
        for (int ks = 0; ks < 4; ++ks) {
            if (ks < 3) b_load(c, ks + 1, bq[(ks + 1) & 1]);
            else        b_load(min(c + 1, K3 - 1), 0, bq[0]);
            compute_ks(buf, ks, bq[ks & 1]);
        }
        if (c + 1 < K3) a_store(buf ^ 1);
        __syncthreads();
    }

    // -------- unscale (W was x2^14) --------
    #pragma unroll
    for (int m = 0; m < 2; ++m)
        #pragma unroll
        for (int t = 0; t < 4; ++t)
            #pragma unroll
            for (int qq = 0; qq < 4; ++qq) acc[m][t][qq] *= WINV;

    // -------- LayerNorm epilogue --------
    // per mrow m: rows r0 = m0w + m*16 + (lane>>2), r1 = r0 + 8
    // tile j: cols = nw*32 + j*8 + (lane&3)*2
    #pragma unroll
    for (int m = 0; m < 2; ++m) {
        float s0 = 0.f, q0 = 0.f, s1 = 0.f, q1 = 0.f;
        #pragma unroll
        for (int t = 0; t < 4; ++t) {
            s0 += acc[m][t][0] + acc[m][t][1];
            q0 += acc[m][t][0] * acc[m][t][0] + acc[m][t][1] * acc[m][t][1];
            s1 += acc[m][t][2] + acc[m][t][3];
            q1 += acc[m][t][2] * acc[m][t][2] + acc[m][t][3] * acc[m][t][3];
        }
        #pragma unroll
        for (int d = 1; d <= 2; d <<= 1) {
            s0 += __shfl_xor_sync(0xffffffffu, s0, d);
            q0 += __shfl_xor_sync(0xffffffffu, q0, d);
            s1 += __shfl_xor_sync(0xffffffffu, s1, d);
            q1 += __shfl_xor_sync(0xffffffffu, q1, d);
        }
        if ((lane & 3) == 0) {
            int r0 = m0w + m * 16 + (lane >> 2);
            s_red[r0 * 8 + nw * 2 + 0] = s0;
            s_red[r0 * 8 + nw * 2 + 1] = q0;
            s_red[(r0 + 8) * 8 + nw * 2 + 0] = s1;
            s_red[(r0 + 8) * 8 + nw * 2 + 1] = q1;
        }
    }
    __syncthreads();

    #pragma unroll
    for (int m = 0; m < 2; ++m) {
        const int r0 = m0w + m * 16 + (lane >> 2);
        const int r1 = r0 + 8;
        const float invC = 1.0f / 128.0f;
        float sA = s_red[r0 * 8 + 0] + s_red[r0 * 8 + 2] + s_red[r0 * 8 + 4] + s_red[r0 * 8 + 6];
        float qA = s_red[r0 * 8 + 1] + s_red[r0 * 8 + 3] + s_red[r0 * 8 + 5] + s_red[r0 * 8 + 7];
        float sB = s_red[r1 * 8 + 0] + s_red[r1 * 8 + 2] + s_red[r1 * 8 + 4] + s_red[r1 * 8 + 6];
        float qB = s_red[r1 * 8 + 1] + s_red[r1 * 8 + 3] + s_red[r1 * 8 + 5] + s_red[r1 * 8 + 7];
        float muA = sA * invC, muB = sB * invC;
        float ivA = rsqrtf(fmaxf(qA * invC - muA * muA, 0.f) + 1e-3f);
        float ivB = rsqrtf(fmaxf(qB * invC - muB * muB, 0.f) + 1e-3f);
        const int gr0 = row0 + r0, gr1 = row0 + r1;
        const bool vA = (gr0 < rows_total) && s_val[r0];
        const bool vB = (gr1 < rows_total) && s_val[r1];
        #pragma unroll
        for (int t = 0; t < 4; ++t) {
            const int cc = nw * 32 + t * 8 + (lane & 3) * 2;
            const float g0 = s_gb[cc], g1 = s_gb[cc + 1];
            const float b0 = s_gb[128 + cc], b1 = s_gb[128 + cc + 1];
            if (gr0 < rows_total) {
                float2 o = make_float2(0.f, 0.f);
                if (vA) {
                    o.x = fmaxf((acc[m][t][0] - muA) * ivA * g0 + b0, 0.f);
                    o.y = fmaxf((acc[m][t][1] - muA) * ivA * g1 + b1, 0.f);
                }
                *(float2*)(out_feat + (size_t)gr0 * 128 + cc) = o;
            }
            if (gr1 < rows_total) {
                float2 o = make_float2(0.f, 0.f);
                if (vB) {
                    o.x = fmaxf((acc[m][t][2] - muB) * ivB * g0 + b0, 0.f);
                    o.y = fmaxf((acc[m][t][3] - muB) * ivB * g1 + b1, 0.f);
                }
                *(float2*)(out_feat + (size_t)gr1 * 128 + cc) = o;
            }
        }
    }

    // -------- coords --------
    if (tid < TILE_M) {
        int r = row0 + tid;
        if (r < rows_total) {
            int b = r / K;
            float col0 = (b < B - 1) ? (float)(b + 1) : 0.f;
            float x = 0.f, y = 0.f, z = 0.f;
            if (s_val[tid]) {
                int src = s_src[tid];
                x = coors[src * 3 + 0];
                y = coors[src * 3 + 1];
                z = coors[src * 3 + 2];
            }
            ((float4*)out_coor)[r] = make_float4(col0, x, y, z);
        }
    }
}

extern "C" void kernel_launch(void* const* d_in, const int* in_sizes, int n_in,
                              void* d_out, int out_size) {
    const float* feat     = (const float*)d_in[0];
    const float* coors    = (const float*)d_in[1];
    const int*   vidx     = (const int*)d_in[2];
    const int*   num_list = (const int*)d_in[3];
    const float* W        = (const float*)d_in[4];
    const float* gamma    = (const float*)d_in[5];
    const float* beta     = (const float*)d_in[6];

    int B    = in_sizes[3];
    int Cout = in_sizes[5];                 // 128
    int M    = in_sizes[1] / 3;
    int K3   = in_sizes[2] / M;             // 27
    int Cin  = (in_sizes[4] / Cout) / K3;   // 64
    int N    = in_sizes[0] / Cin;

    int rows_total = out_size / (Cout + 4); // B*K
    int K = rows_total / B;

    float* out_feat = (float*)d_out;
    float* out_coor = out_feat + (size_t)rows_total * Cout;

    int wf_total = K3 * 4096;               // uint32 (=half2) entries
    prep_w<<<(wf_total + 255) / 256, 256>>>(W, wf_total);

    cudaFuncSetAttribute(fused_mma_kernel,
                         cudaFuncAttributeMaxDynamicSharedMemorySize, SM_TOTAL);
    int grid = (rows_total + TILE_M - 1) / TILE_M;
    fused_mma_kernel<<<grid, NTH, SM_TOTAL>>>(feat, coors, vidx, num_list, gamma, beta,
                                              out_feat, out_coor,
                                              N, M, K3, B, K, rows_total);
}

// round 15
// speedup vs baseline: 1.0055x; 1.0055x over previous
#include <cuda_runtime.h>
#include <cuda_fp16.h>
#include <cstdint>

// DynamicPointConvBackBone via mma.sync (base-ISA HMMA; tcgen05 unavailable on
// the harness's compute_103 PTX target).
// Resample-first: only B*K rows computed. GEMM [8192 x 1728] @ [1728 x 128]
// in single-pass fp16 (W pre-scaled by 2^14), fp32 accumulate.
// R14: SPLIT-K = 2. Each 32-row tile is computed by two CTAs covering half the
// K chunks each; fp32 partials land in an L2-resident scratch; a second kernel
// reduces the two partials, unscales, applies LayerNorm(eps=1e-3)+gamma/beta+
// ReLU + validity, and writes coords.

#define TILE_M 32
#define NTH    256
#define IDXP   28
#define MAXCH  28
#define CHUNK  64        // = Cin
#define ATB    4096      // A tile bytes (32 rows x 64 fp16 x 2B)
#define BTB    16384     // B tile bytes (64 k x 128 n x 2B)
#define WSCALE 16384.0f
#define WINV   (1.0f / 16384.0f)
#define SPLITK 2
#define MAXROWS 8192

// dynamic smem layout (main kernel)
#define SM_A   0
#define SM_B   (SM_A + 2 * ATB)              // 8192
#define SM_IDX (SM_B + 2 * BTB)              // 40960
#define SM_SRC (SM_IDX + TILE_M * IDXP * 4)  // 44544
#define SM_TOTAL (SM_SRC + TILE_M * 4)       // 44672

__device__ __align__(16) __half g_w[MAXCH * CHUNK * 128];        // [k][n] fp16, x2^14
__device__ __align__(16) float  g_part[SPLITK * MAXROWS * 128];  // split-K partials

static __device__ __forceinline__ uint32_t smem_u32(const void* p) {
    uint32_t a;
    asm("{ .reg .u64 t; cvta.to.shared.u64 t, %1; cvt.u32.u64 %0, t; }" : "=r"(a) : "l"(p));
    return a;
}
static __device__ __forceinline__ uint32_t pack_h2(float lo, float hi) {
    uint32_t r;
    asm("cvt.rn.f16x2.f32 %0, %1, %2;" : "=r"(r) : "f"(hi), "f"(lo));
    return r;
}
static __device__ __forceinline__ void cpasync16(uint32_t dst, const void* src) {
    asm volatile("cp.async.cg.shared.global [%0], [%1], 16;" :: "r"(dst), "l"(src) : "memory");
}
static __device__ __forceinline__ void cpwait_all() {
    asm volatile("cp.async.wait_all;" ::: "memory");
}
static __device__ __forceinline__ void ldsm4(uint32_t* r, uint32_t addr) {
    asm volatile("ldmatrix.sync.aligned.m8n8.x4.shared.b16 {%0,%1,%2,%3}, [%4];"
                 : "=r"(r[0]), "=r"(r[1]), "=r"(r[2]), "=r"(r[3]) : "r"(addr));
}
static __device__ __forceinline__ void ldsm4t(uint32_t* r, uint32_t addr) {
    asm volatile("ldmatrix.sync.aligned.m8n8.x4.trans.shared.b16 {%0,%1,%2,%3}, [%4];"
                 : "=r"(r[0]), "=r"(r[1]), "=r"(r[2]), "=r"(r[3]) : "r"(addr));
}
static __device__ __forceinline__ void mma16816(float* d, const uint32_t* a,
                                                uint32_t b0, uint32_t b1) {
    asm volatile(
        "mma.sync.aligned.m16n8k16.row.col.f32.f16.f16.f32 "
        "{%0,%1,%2,%3}, {%4,%5,%6,%7}, {%8,%9}, {%0,%1,%2,%3};"
        : "+f"(d[0]), "+f"(d[1]), "+f"(d[2]), "+f"(d[3])
        : "r"(a[0]), "r"(a[1]), "r"(a[2]), "r"(a[3]), "r"(b0), "r"(b1));
}

// ---------------- prep: W -> fp16 scaled by 2^14, [k][n] ----------------
__global__ void prep_w(const float* __restrict__ W, int total) {
    int idx = blockIdx.x * blockDim.x + threadIdx.x;
    if (idx >= total) return;
    g_w[idx] = __float2half(W[idx] * WSCALE);
}

// ---------------- main split-K GEMM kernel ----------------
__global__ __launch_bounds__(NTH, 2)
void gemm_splitk_kernel(
    const float* __restrict__ feat,   // [N, 64]
    const int*   __restrict__ vidx,   // [M, K3]
    const int*   __restrict__ nums,   // [B]
    int N, int M, int K3, int B, int K, int rows_total)
{
    extern __shared__ __align__(128) char sm[];
    const uint32_t smb = smem_u32(sm);
    const int tid  = threadIdx.x;
    const int wid  = tid >> 5;
    const int lane = tid & 31;

    const int rt   = blockIdx.x >> 1;        // row tile
    const int half = blockIdx.x & 1;         // split-K half
    const int row0 = rt * TILE_M;

    const int per     = (K3 + SPLITK - 1) / SPLITK;
    const int c_begin = half * per;
    const int c_end   = min(K3, c_begin + per);

    int* s_idx = (int*)(sm + SM_IDX);
    int* s_src = (int*)(sm + SM_SRC);

    // per-row source index (validity handled in reduce kernel)
    if (tid < TILE_M) {
        int r = row0 + tid;
        int src = 0;
        if (r < rows_total) {
            int b = r / K;
            int j = r - b * K;
            int off = 0;
            for (int i = 0; i < b; ++i) off += nums[i];
            src = max(0, min(off + j, M - 1));
        }
        s_src[tid] = src;
    }
    __syncthreads();

    // neighbor indices for this CTA's chunk range
    for (int i = tid; i < TILE_M * (c_end - c_begin); i += NTH) {
        int rr = i / (c_end - c_begin);
        int cc = i - rr * (c_end - c_begin) + c_begin;
        int v = vidx[(long long)s_src[rr] * K3 + cc];
        s_idx[rr * IDXP + cc] = (v < 0) ? -1 : min(v, N - 1);
    }
    __syncthreads();

    // -------- loaders --------
    const int arow = tid >> 3;          // gather row 0..31
    const int aseg = tid & 7;           // 32B segment of 256B fp32 feature row
    float4 pa0, pa1;

    auto a_issue = [&](int c) {
        int gi = s_idx[arow * IDXP + c];
        if (gi >= 0) {
            const float4* src = (const float4*)(feat + (size_t)gi * CHUNK) + aseg * 2;
            pa0 = __ldg(src + 0);
            pa1 = __ldg(src + 1);
        } else {
            pa0 = pa1 = make_float4(0.f, 0.f, 0.f, 0.f);
        }
    };
    auto a_store = [&](int buf) {
        uint4 h;
        h.x = pack_h2(pa0.x, pa0.y);
        h.y = pack_h2(pa0.z, pa0.w);
        h.z = pack_h2(pa1.x, pa1.y);
        h.w = pack_h2(pa1.z, pa1.w);
        const int o = arow * 128 + ((aseg ^ (arow & 7)) << 4);
        *(uint4*)(sm + SM_A + buf * ATB + o) = h;
    };
    auto b_issue = [&](int c, int buf) {
        const char* srcB = (const char*)g_w + (size_t)c * BTB;
        uint32_t dB = smb + SM_B + buf * BTB;
        #pragma unroll
        for (int j = 0; j < 4; ++j) {
            int idx  = tid + j * NTH;
            int krow = idx >> 4;
            int col  = idx & 15;
            int dof  = krow * 256 + ((col ^ (krow & 7)) << 4);
            int so   = krow * 256 + col * 16;
            cpasync16(dB + dof, srcB + so);
        }
    };

    // -------- compute (per warp: m16 x n32) --------
    const int mw = wid & 1, nw = wid >> 1;   // 2 m-warps x 4 n-warps
    const int m0 = mw * 16;
    float acc[4][4];
    #pragma unroll
    for (int t = 0; t < 4; ++t)
        #pragma unroll
        for (int q = 0; q < 4; ++q) acc[t][q] = 0.f;

    const int a_r  = m0 + (lane & 15);
    const int a_hi = (lane >> 4);
    const int k_l  = (lane & 15);

    auto mma_chunk = [&](int buf) {
        const uint32_t aB = smb + SM_A + buf * ATB + a_r * 128;
        const uint32_t bB = smb + SM_B + buf * BTB;
        const int asw = (a_r & 7);
        #pragma unroll
        for (int ks = 0; ks < 4; ++ks) {
            uint32_t ah[4];
            const int acol = ks * 2 + a_hi;
            ldsm4(ah, aB + (uint32_t)((acol ^ asw) << 4));
            const int krow = ks * 16 + k_l;
            const uint32_t brow = (uint32_t)(krow * 256);
            const int ksw = (krow & 7);
            #pragma unroll
            for (int tt = 0; tt < 2; ++tt) {
                uint32_t bh[4];
                const int bcol = nw * 4 + tt * 2 + a_hi;
                ldsm4t(bh, brow + bB + (uint32_t)((bcol ^ ksw) << 4));
                mma16816(acc[2 * tt],     ah, bh[0], bh[1]);
                mma16816(acc[2 * tt + 1], ah, bh[2], bh[3]);
            }
        }
    };

    // -------- pipelined main loop over [c_begin, c_end) --------
    b_issue(c_begin, 0);
    a_issue(c_begin);
    a_store(0);
    cpwait_all();
    __syncthreads();

    for (int c = c_begin; c < c_end; ++c) {
        const int buf = (c - c_begin) & 1;
        const bool nxt = (c + 1) < c_end;
        if (nxt) { b_issue(c + 1, buf ^ 1); a_issue(c + 1); }
        mma_chunk(buf);
        if (nxt) a_store(buf ^ 1);
        cpwait_all();
        __syncthreads();
    }

    // -------- write partials (still W-scaled fp32) --------
    float* part = g_part + (size_t)half * MAXROWS * 128;
    {
        const int r0 = m0 + (lane >> 2);
        const int r1 = r0 + 8;
        const int gr0 = row0 + r0, gr1 = row0 + r1;
        #pragma unroll
        for (int t = 0; t < 4; ++t) {
            const int c = nw * 32 + (t >> 1) * 16 + (t & 1) * 8 + (lane & 3) * 2;
            if (gr0 < rows_total)
                *(float2*)(part + (size_t)gr0 * 128 + c) = make_float2(acc[t][0], acc[t][1]);
            if (gr1 < rows_total)
                *(float2*)(part + (size_t)gr1 * 128 + c) = make_float2(acc[t][2], acc[t][3]);
        }
    }
}

// ---------------- reduce + LayerNorm + coords kernel ----------------
__global__ __launch_bounds__(256, 4)
void reduce_ln_kernel(
    const float* __restrict__ coors,  // [M, 3]
    const int*   __restrict__ nums,   // [B]
    const float* __restrict__ gamma,  // [128]
    const float* __restrict__ beta,   // [128]
    float* __restrict__ out_feat,     // [rows_total, 128]
    float* __restrict__ out_coor,     // [rows_total, 4]
    int M, int B, int K, int rows_total)
{
    const int row  = blockIdx.x * 8 + (threadIdx.x >> 5);
    const int lane = threadIdx.x & 31;
    if (row >= rows_total) return;

    float4 p0 = *(const float4*)(g_part + (size_t)row * 128 + lane * 4);
    float4 p1 = *(const float4*)(g_part + (size_t)MAXROWS * 128 + (size_t)row * 128 + lane * 4);
    float4 v;
    v.x = (p0.x + p1.x) * WINV;
    v.y = (p0.y + p1.y) * WINV;
    v.z = (p0.z + p1.z) * WINV;
    v.w = (p0.w + p1.w) * WINV;

    float s = v.x + v.y + v.z + v.w;
    float q = v.x * v.x + v.y * v.y + v.z * v.z + v.w * v.w;
    #pragma unroll
    for (int d = 16; d >= 1; d >>= 1) {
        s += __shfl_xor_sync(0xffffffffu, s, d);
        q += __shfl_xor_sync(0xffffffffu, q, d);
    }
    const float invC = 1.0f / 128.0f;
    float mu = s * invC;
    float iv = rsqrtf(fmaxf(q * invC - mu * mu, 0.f) + 1e-3f);

    // validity / source
    int b = row / K;
    int j = row - b * K;
    int off = 0;
    for (int i = 0; i < b; ++i) off += nums[i];
    bool valid = j < min(nums[b], K);
    int src = max(0, min(off + j, M - 1));

    float4 g = *(const float4*)(gamma + lane * 4);
    float4 bb = *(const float4*)(beta + lane * 4);
    float4 o = make_float4(0.f, 0.f, 0.f, 0.f);
    if (valid) {
        o.x = fmaxf((v.x - mu) * iv * g.x + bb.x, 0.f);
        o.y = fmaxf((v.y - mu) * iv * g.y + bb.y, 0.f);
        o.z = fmaxf((v.z - mu) * iv * g.z + bb.z, 0.f);
        o.w = fmaxf((v.w - mu) * iv * g.w + bb.w, 0.f);
    }
    *(float4*)(out_feat + (size_t)row * 128 + lane * 4) = o;

    if (lane == 0) {
        float col0 = (b < B - 1) ? (float)(b + 1) : 0.f;
        float x = 0.f, y = 0.f, z = 0.f;
        if (valid) {
            x = coors[src * 3 + 0];
            y = coors[src * 3 + 1];
            z = coors[src * 3 + 2];
        }
        ((float4*)out_coor)[row] = make_float4(col0, x, y, z);
    }
}

extern "C" void kernel_launch(void* const* d_in, const int* in_sizes, int n_in,
                              void* d_out, int out_size) {
    const float* feat     = (const float*)d_in[0];
    const float* coors    = (const float*)d_in[1];
    const int*   vidx     = (const int*)d_in[2];
    const int*   num_list = (const int*)d_in[3];
    const float* W        = (const float*)d_in[4];
    const float* gamma    = (const float*)d_in[5];
    const float* beta     = (const float*)d_in[6];

    int B    = in_sizes[3];
    int Cout = in_sizes[5];                 // 128
    int M    = in_sizes[1] / 3;
    int K3   = in_sizes[2] / M;             // 27
    int Cin  = (in_sizes[4] / Cout) / K3;   // 64
    int N    = in_sizes[0] / Cin;
    int Ktot = K3 * Cin;

    int rows_total = out_size / (Cout + 4); // B*K
    int K = rows_total / B;

    float* out_feat = (float*)d_out;
    float* out_coor = out_feat + (size_t)rows_total * Cout;

    prep_w<<<(Ktot * Cout + 255) / 256, 256>>>(W, Ktot * Cout);

    cudaFuncSetAttribute(gemm_splitk_kernel,
                         cudaFuncAttributeMaxDynamicSharedMemorySize, SM_TOTAL);
    int rowtiles = (rows_total + TILE_M - 1) / TILE_M;
    gemm_splitk_kernel<<<rowtiles * SPLITK, NTH, SM_TOTAL>>>(
        feat, vidx, num_list, N, M, K3, B, K, rows_total);

    int rb = (rows_total + 7) / 8;
    reduce_ln_kernel<<<rb, 256>>>(coors, num_list, gamma, beta,
                                  out_feat, out_coor, M, B, K, rows_total);
}